// round 14
// baseline (speedup 1.0000x reference)
#include <cuda_runtime.h>
#include <cuda_bf16.h>
#include <math.h>
#include <stdint.h>

#define N_VARS 50000
#define HID 128
#define N_EDGES 400000
#define NP 50048            // 391 * 128
#define NBLK (NP / 128)     // 391
#define STEPS 4
#define BN_EPS 1e-5f

// ---------------- static device scratch ----------------
__device__ float g_hA[NP * HID];
__device__ float g_hB[NP * HID];
__device__ float g_c[NP * HID];
__device__ float g_rec[NP * HID];
__device__ float g_degf[NP];
__device__ int   g_degi[NP];
__device__ int   g_off[NP + 1];
__device__ int   g_cur[NP];
__device__ int   g_adj[2 * N_EDGES];
// Weights in mma B-fragment order: uint4 = {bHi(k,k+1), bHi(k+8,k+9), bLo(k,k+1), bLo(k+8,k+9)}
// index = (((chunkSel)*4 + ks)*16 + n8)*32 + lane
__device__ __align__(16) uint4 g_W1r[4 * 4 * 16 * 32];          // 8192  (128 KB)
__device__ __align__(16) uint4 g_W2r[4 * 4 * 4 * 16 * 32];      // 32768 (512 KB)
__device__ __align__(16) __nv_bfloat16 g_X1h[NP * 256];         // [agg | deg*h] hi
__device__ __align__(16) __nv_bfloat16 g_X1l[NP * 256];
// ping-pong: [BN(rec) | h] — gates reads par, writes h-half of par^1
__device__ __align__(16) __nv_bfloat16 g_X2h[2][NP * 256];
__device__ __align__(16) __nv_bfloat16 g_X2l[2][NP * 256];
__device__ float g_bias[4 * HID];
__device__ float g_stats[2 * HID];

__device__ __forceinline__ float sigf(float x) { return 1.0f / (1.0f + expf(-x)); }

__device__ __forceinline__ uint32_t smem_u32(const void* p) {
    uint32_t a;
    asm("{ .reg .u64 t; cvta.to.shared.u64 t, %1; cvt.u32.u64 %0, t; }" : "=r"(a) : "l"(p));
    return a;
}
#define SWZ(o) ((o) ^ (((o) >> 3) & 0x70))

#define LDSM4(R, A) \
    asm volatile("ldmatrix.sync.aligned.m8n8.x4.shared.b16 {%0,%1,%2,%3}, [%4];" \
                 : "=r"((R)[0]), "=r"((R)[1]), "=r"((R)[2]), "=r"((R)[3]) : "r"(A))

#define MMA(C, A, B0, B1) \
    asm volatile("mma.sync.aligned.m16n8k16.row.col.f32.bf16.bf16.f32 " \
                 "{%0,%1,%2,%3},{%4,%5,%6,%7},{%8,%9},{%0,%1,%2,%3};" \
                 : "+f"((C)[0]), "+f"((C)[1]), "+f"((C)[2]), "+f"((C)[3]) \
                 : "r"((A)[0]), "r"((A)[1]), "r"((A)[2]), "r"((A)[3]), "r"(B0), "r"(B1))

#define CP16(dst_u32, src_ptr) \
    asm volatile("cp.async.cg.shared.global [%0], [%1], 16;" \
                 :: "r"(dst_u32), "l"(src_ptr))
#define CP_COMMIT() asm volatile("cp.async.commit_group;")
#define CP_WAIT(n)  asm volatile("cp.async.wait_group %0;" :: "n"(n))

union Pack8 { __nv_bfloat16 b[8]; uint4 u; };
__device__ __forceinline__ void split8(float4 a, float4 b, uint4& hi, uint4& lo) {
    float v[8] = {a.x, a.y, a.z, a.w, b.x, b.y, b.z, b.w};
    Pack8 ph, pl;
#pragma unroll
    for (int i = 0; i < 8; i++) {
        __nv_bfloat16 h = __float2bfloat16(v[i]);
        ph.b[i] = h;
        pl.b[i] = __float2bfloat16(v[i] - __bfloat162float(h));
    }
    hi = ph.u; lo = pl.u;
}
union Pack4 { __nv_bfloat16 b[4]; uint2 u; };
__device__ __forceinline__ void split4(float4 a, uint2& hi, uint2& lo) {
    float v[4] = {a.x, a.y, a.z, a.w};
    Pack4 ph, pl;
#pragma unroll
    for (int i = 0; i < 4; i++) {
        __nv_bfloat16 h = __float2bfloat16(v[i]);
        ph.b[i] = h;
        pl.b[i] = __float2bfloat16(v[i] - __bfloat162float(h));
    }
    hi = ph.u; lo = pl.u;
}
__device__ __forceinline__ uint32_t split2(float x, float y, uint32_t& lo) {
    __nv_bfloat16 hx = __float2bfloat16(x), hy = __float2bfloat16(y);
    __nv_bfloat16 lx = __float2bfloat16(x - __bfloat162float(hx));
    __nv_bfloat16 ly = __float2bfloat16(y - __bfloat162float(hy));
    uint16_t uhx = *(uint16_t*)&hx, uhy = *(uint16_t*)&hy;
    uint16_t ulx = *(uint16_t*)&lx, uly = *(uint16_t*)&ly;
    lo = (uint32_t)ulx | ((uint32_t)uly << 16);
    return (uint32_t)uhx | ((uint32_t)uhy << 16);
}

// A-only smem stages: A_hi @0, A_lo @16384 — 32 KB per stage, 3 stages
#define STAGE_SZ 32768
#define SMEMSZ (1024 + 3 * STAGE_SZ)

// ---------------- prep: weights in mma-fragment order, fused bias ----------------
__global__ void prep_kernel(const float* __restrict__ W_msg,
                            const float* __restrict__ W_ih,
                            const float* __restrict__ W_hh,
                            const float* __restrict__ b_ih,
                            const float* __restrict__ b_hh) {
    int t = blockIdx.x * blockDim.x + threadIdx.x;
    int stride = gridDim.x * blockDim.x;
    // W1r: 4 chunks x 4 ks x 16 n8 x 32 lanes
    for (int i = t; i < 8192; i += stride) {
        int lane = i & 31, n8 = (i >> 5) & 15, ks = (i >> 9) & 3, c = (i >> 11) & 3;
        int n = n8 * 8 + (lane >> 2);
        int kb = c * 64 + ks * 16 + (lane & 3) * 2;
        float w0 = W_msg[n * 256 + kb],     w1 = W_msg[n * 256 + kb + 1];
        float w2 = W_msg[n * 256 + kb + 8], w3 = W_msg[n * 256 + kb + 9];
        uint4 f;
        uint32_t lo;
        f.x = split2(w0, w1, lo); f.z = lo;
        f.y = split2(w2, w3, lo); f.w = lo;
        g_W1r[i] = f;
    }
    // W2r: 4 by x 4 chunks x 4 ks x 16 n8 x 32 lanes ; W2 rows n=4j+g permuted
    for (int i = t; i < 32768; i += stride) {
        int lane = i & 31, n8 = (i >> 5) & 15, ks = (i >> 9) & 3, c = (i >> 11) & 3, by = (i >> 13) & 3;
        int n = by * 128 + n8 * 8 + (lane >> 2);
        int j = n >> 2, g = n & 3;
        int wrow = g * HID + j;
        int kb = c * 64 + ks * 16 + (lane & 3) * 2;
        float w[4];
#pragma unroll
        for (int q = 0; q < 4; q++) {
            int k = kb + (q >> 1) * 8 + (q & 1);
            w[q] = (k < HID) ? W_ih[wrow * HID + k] : W_hh[wrow * HID + (k - HID)];
        }
        uint4 f;
        uint32_t lo;
        f.x = split2(w[0], w[1], lo); f.z = lo;
        f.y = split2(w[2], w[3], lo); f.w = lo;
        g_W2r[i] = f;
    }
    for (int i = t; i < 4 * HID; i += stride) g_bias[i] = b_ih[i] + b_hh[i];
}

// ---------------- CSR build ----------------
__global__ void degcnt_kernel(const int* __restrict__ ei) {
    int i = blockIdx.x * blockDim.x + threadIdx.x;
    if (i < 2 * N_EDGES) atomicAdd(&g_degi[ei[i]], 1);
}

__global__ void scan_kernel() {       // single block, 1024 threads
    __shared__ int part[1024];
    int t = threadIdx.x;
    const int CH = (N_VARS + 1023) / 1024;
    int base = t * CH;
    int s = 0;
    for (int i = 0; i < CH; i++) {
        int idx = base + i;
        if (idx < N_VARS) s += g_degi[idx];
    }
    part[t] = s;
    __syncthreads();
    int val = s;
#pragma unroll
    for (int d = 1; d < 1024; d <<= 1) {
        int v = (t >= d) ? part[t - d] : 0;
        __syncthreads();
        part[t] += v;
        __syncthreads();
    }
    int excl = part[t] - val;
    int run = excl;
    for (int i = 0; i < CH; i++) {
        int idx = base + i;
        if (idx < N_VARS) {
            g_off[idx] = run;
            int d = g_degi[idx];
            g_degf[idx] = (float)d;
            run += d;
        }
    }
    if (t == 1023) g_off[N_VARS] = run;
}

__global__ void fill_kernel(const int* __restrict__ ei) {
    int i = blockIdx.x * blockDim.x + threadIdx.x;
    if (i >= 2 * N_EDGES) return;
    int s, d;
    if (i < N_EDGES) { s = ei[i]; d = ei[N_EDGES + i]; }
    else             { s = ei[i]; d = ei[i - N_EDGES]; }
    int pos = atomicAdd(&g_cur[d], 1);
    g_adj[g_off[d] + pos] = s;
}

// ---------------- h0 split -> X2[0] h-part (once) ----------------
__global__ void h0split(const float* __restrict__ hin) {
    int idx = blockIdx.x * blockDim.x + threadIdx.x;
    if (idx >= NP * 16) return;
    int row = idx >> 4, i = idx & 15;
    const float* src = &hin[(size_t)row * HID + i * 8];
    float4 v0 = *(const float4*)src, v1 = *(const float4*)(src + 4);
    uint4 hi, lo; split8(v0, v1, hi, lo);
    ((uint4*)g_X2h[0])[row * 32 + 16 + i] = hi;
    ((uint4*)g_X2l[0])[row * 32 + 16 + i] = lo;
}

// ---------------- CSR gather -> X1 = split([agg | deg*h]) ----------------
__global__ void gather_kernel(const float* __restrict__ hin) {
    int w = (blockIdx.x * blockDim.x + threadIdx.x) >> 5;
    int lane = threadIdx.x & 31;
    if (w >= N_VARS) return;
    int e = g_off[w], end = g_off[w + 1];
    int c4 = lane * 4;
    float4 s0 = make_float4(0, 0, 0, 0), s1 = make_float4(0, 0, 0, 0);
    float4 s2 = make_float4(0, 0, 0, 0), s3 = make_float4(0, 0, 0, 0);
    for (; e + 4 <= end; e += 4) {
        int u0 = g_adj[e], u1 = g_adj[e + 1], u2 = g_adj[e + 2], u3 = g_adj[e + 3];
        float4 a = *(const float4*)&hin[(size_t)u0 * HID + c4];
        float4 b = *(const float4*)&hin[(size_t)u1 * HID + c4];
        float4 c = *(const float4*)&hin[(size_t)u2 * HID + c4];
        float4 d = *(const float4*)&hin[(size_t)u3 * HID + c4];
        s0.x += a.x; s0.y += a.y; s0.z += a.z; s0.w += a.w;
        s1.x += b.x; s1.y += b.y; s1.z += b.z; s1.w += b.w;
        s2.x += c.x; s2.y += c.y; s2.z += c.z; s2.w += c.w;
        s3.x += d.x; s3.y += d.y; s3.z += d.z; s3.w += d.w;
    }
    for (; e < end; e++) {
        int u = g_adj[e];
        float4 a = *(const float4*)&hin[(size_t)u * HID + c4];
        s0.x += a.x; s0.y += a.y; s0.z += a.z; s0.w += a.w;
    }
    s0.x += s1.x + s2.x + s3.x; s0.y += s1.y + s2.y + s3.y;
    s0.z += s1.z + s2.z + s3.z; s0.w += s1.w + s2.w + s3.w;
    uint2 hi, lo;
    split4(s0, hi, lo);
    ((uint2*)g_X1h)[w * 64 + lane] = hi;
    ((uint2*)g_X1l)[w * 64 + lane] = lo;
    float d = g_degf[w];
    float4 hv = *(const float4*)&hin[(size_t)w * HID + c4];
    hv.x *= d; hv.y *= d; hv.z *= d; hv.w *= d;
    split4(hv, hi, lo);
    ((uint2*)g_X1h)[w * 64 + 32 + lane] = hi;
    ((uint2*)g_X1l)[w * 64 + 32 + lane] = lo;
}

// ---------------- cp.async A-tile staging ----------------
__device__ __forceinline__ void stage_A(uint32_t sbase,
                                        const uint4* __restrict__ Ah,
                                        const uint4* __restrict__ Al,
                                        int aBase32, int k8, int tid) {
#pragma unroll
    for (int idx = tid; idx < 1024; idx += 512) {
        int row = idx >> 3, i = idx & 7;
        uint32_t sw = SWZ((uint32_t)(row * 128 + i * 16));
        CP16(sbase + sw,         Ah + aBase32 + row * 32 + k8 + i);
        CP16(sbase + 16384 + sw, Al + aBase32 + row * 32 + k8 + i);
    }
}

// ---------------- warp-tile compute: A from smem (LDSM), B frags via LDG ----------------
__device__ __forceinline__ void chunk_compute(uint32_t sb, const uint4* __restrict__ Wr,
                                              int fragBase, int n8base,
                                              int warpRow, int lane, float acc[2][4][4]) {
#pragma unroll
    for (int ks = 0; ks < 4; ks++) {
        uint32_t aH[2][4], aL[2][4];
#pragma unroll
        for (int mt = 0; mt < 2; mt++) {
            uint32_t off = (uint32_t)((warpRow + mt * 16 + (lane & 15)) * 128
                                      + ks * 32 + ((lane >> 4) & 1) * 16);
            uint32_t sw = SWZ(off);
            LDSM4(aH[mt], sb + sw);
            LDSM4(aL[mt], sb + 16384 + sw);
        }
#pragma unroll
        for (int nn = 0; nn < 4; nn++) {
            uint4 f = __ldg(&Wr[fragBase + (ks * 16 + n8base + nn) * 32 + lane]);
#pragma unroll
            for (int mt = 0; mt < 2; mt++) {
                float* c = acc[mt][nn];
                MMA(c, aH[mt], f.x, f.y);
                MMA(c, aH[mt], f.z, f.w);
                MMA(c, aL[mt], f.x, f.y);
            }
        }
    }
}

// ---------------- shared GEMM pipeline: A-only stages, B-in-registers ----------------
#define GEMM_PIPELINE(Ah, Al, ABASE, Wr, FB)                                           \
    stage_A(sb,                Ah, Al, ABASE,  0, tid); CP_COMMIT();                   \
    stage_A(sb + STAGE_SZ,     Ah, Al, ABASE,  8, tid); CP_COMMIT();                   \
    stage_A(sb + 2 * STAGE_SZ, Ah, Al, ABASE, 16, tid); CP_COMMIT();                   \
    CP_WAIT(2); __syncthreads();                                                       \
    chunk_compute(sb, Wr, (FB), n8base, warpRow, lane, acc);                           \
    __syncthreads();                                                                   \
    stage_A(sb, Ah, Al, ABASE, 24, tid); CP_COMMIT();                                  \
    CP_WAIT(2); __syncthreads();                                                       \
    chunk_compute(sb + STAGE_SZ, Wr, (FB) + 2048, n8base, warpRow, lane, acc);         \
    CP_WAIT(1); __syncthreads();                                                       \
    chunk_compute(sb + 2 * STAGE_SZ, Wr, (FB) + 4096, n8base, warpRow, lane, acc);     \
    CP_WAIT(0); __syncthreads();                                                       \
    chunk_compute(sb, Wr, (FB) + 6144, n8base, warpRow, lane, acc);                    \
    __syncthreads();

// ---------------- rec = (X1 @ W1^T) * var_reg, with fused BN stats ----------------
__global__ void __launch_bounds__(512, 1)
rec_mma(const float* __restrict__ var_reg) {
    extern __shared__ char smraw[];
    uint32_t sb0 = smem_u32(smraw);
    uint32_t sb = (sb0 + 1023) & ~1023u;
    const int tid = threadIdx.x;
    const int wid = tid >> 5, lane = tid & 31;
    const int rowBase = blockIdx.x * 128;
    const int warpRow = (wid >> 2) * 32, warpCol = (wid & 3) * 32;
    const int n8base = (wid & 3) * 4;

    float acc[2][4][4];
#pragma unroll
    for (int m = 0; m < 2; m++)
#pragma unroll
        for (int n = 0; n < 4; n++)
#pragma unroll
            for (int c = 0; c < 4; c++) acc[m][n][c] = 0.f;

    GEMM_PIPELINE((const uint4*)g_X1h, (const uint4*)g_X1l, rowBase * 32, g_W1r, 0)

    // epilogue: scale by var_reg, store rec, fused column stats
    float s[4][2] = {}, q[4][2] = {};
#pragma unroll
    for (int mt = 0; mt < 2; mt++) {
        int r0 = rowBase + warpRow + mt * 16 + (lane >> 2);
        int r1 = r0 + 8;
        float vr0 = (r0 < N_VARS) ? var_reg[r0] : 0.f;
        float vr1 = (r1 < N_VARS) ? var_reg[r1] : 0.f;
#pragma unroll
        for (int n8 = 0; n8 < 4; n8++) {
            int col = warpCol + n8 * 8 + 2 * (lane & 3);
            float* c = acc[mt][n8];
            float v00 = c[0] * vr0, v01 = c[1] * vr0;
            float v10 = c[2] * vr1, v11 = c[3] * vr1;
            *(float2*)&g_rec[(size_t)r0 * HID + col] = make_float2(v00, v01);
            *(float2*)&g_rec[(size_t)r1 * HID + col] = make_float2(v10, v11);
            s[n8][0] += v00 + v10;  q[n8][0] += v00 * v00 + v10 * v10;
            s[n8][1] += v01 + v11;  q[n8][1] += v01 * v01 + v11 * v11;
        }
    }
#pragma unroll
    for (int o = 4; o <= 16; o <<= 1) {
#pragma unroll
        for (int n8 = 0; n8 < 4; n8++) {
#pragma unroll
            for (int p = 0; p < 2; p++) {
                s[n8][p] += __shfl_xor_sync(0xffffffffu, s[n8][p], o);
                q[n8][p] += __shfl_xor_sync(0xffffffffu, q[n8][p], o);
            }
        }
    }
    if (lane < 4) {
#pragma unroll
        for (int n8 = 0; n8 < 4; n8++) {
#pragma unroll
            for (int p = 0; p < 2; p++) {
                int col = warpCol + n8 * 8 + 2 * lane + p;
                atomicAdd(&g_stats[col], s[n8][p]);
                atomicAdd(&g_stats[HID + col], q[n8][p]);
            }
        }
    }
}

// ---------------- X2[par] rec-half = bf16-split of BN(rec); BN coeffs in-block ----------------
__global__ void x2_convert(int par, const float* __restrict__ gamma,
                           const float* __restrict__ beta) {
    __shared__ float sA[HID], sB[HID];
    int t = threadIdx.x;
    if (t < HID) {
        float mean = g_stats[t] * (1.0f / N_VARS);
        float var = g_stats[HID + t] * (1.0f / N_VARS) - mean * mean;
        float a = gamma[t] * rsqrtf(var + BN_EPS);
        sA[t] = a;
        sB[t] = beta[t] - mean * a;
    }
    __syncthreads();
    int idx = blockIdx.x * blockDim.x + t;
    if (idx >= NP * 16) return;
    int row = idx >> 4;
    int k = (idx & 15) * 8;
    const float* src = &g_rec[(size_t)row * HID + k];
    float4 v0 = *(const float4*)src, v1 = *(const float4*)(src + 4);
    float4 a0 = *(const float4*)&sA[k], a1 = *(const float4*)&sA[k + 4];
    float4 b0 = *(const float4*)&sB[k], b1 = *(const float4*)&sB[k + 4];
    v0.x = fmaf(v0.x, a0.x, b0.x); v0.y = fmaf(v0.y, a0.y, b0.y);
    v0.z = fmaf(v0.z, a0.z, b0.z); v0.w = fmaf(v0.w, a0.w, b0.w);
    v1.x = fmaf(v1.x, a1.x, b1.x); v1.y = fmaf(v1.y, a1.y, b1.y);
    v1.z = fmaf(v1.z, a1.z, b1.z); v1.w = fmaf(v1.w, a1.w, b1.w);
    uint4 hi, lo; split8(v0, v1, hi, lo);
    ((uint4*)g_X2h[par])[row * 32 + (idx & 15)] = hi;
    ((uint4*)g_X2l[par])[row * 32 + (idx & 15)] = lo;
}

// ---------------- gates = X2[par] @ W2^T + LSTM pointwise; split(h) -> X2[par^1] ----------------
// grid = dim3(4, NBLK)
__global__ void __launch_bounds__(512, 1)
gates_mma(float* __restrict__ hout, int par) {
    extern __shared__ char smraw[];
    uint32_t sb0 = smem_u32(smraw);
    uint32_t sb = (sb0 + 1023) & ~1023u;
    char* smp = smraw + (sb - sb0);
    const int tid = threadIdx.x;
    const int wid = tid >> 5, lane = tid & 31;
    const int by = blockIdx.x;
    const int bx = blockIdx.y;
    const int rowBase = bx * 128;
    const int warpRow = (wid >> 2) * 32, warpCol = (wid & 3) * 32;
    const int n8base = (wid & 3) * 4;

    // reset BN stats for the next step (after x2_convert consumed them)
    if (bx == 0 && by == 0 && tid < 2 * HID) g_stats[tid] = 0.f;

    float acc[2][4][4];
#pragma unroll
    for (int m = 0; m < 2; m++)
#pragma unroll
        for (int n = 0; n < 4; n++)
#pragma unroll
            for (int c = 0; c < 4; c++) acc[m][n][c] = 0.f;

    GEMM_PIPELINE((const uint4*)g_X2h[par], (const uint4*)g_X2l[par],
                  rowBase * 32, g_W2r, by * 8192)

    // stage gate tile to smem overlay, then fused LSTM pointwise
    float* Cs = (float*)smp;                   // 128 x 128 fp32 overlay (64 KB < 96 KB stages)
#pragma unroll
    for (int mt = 0; mt < 2; mt++) {
        int r0 = warpRow + mt * 16 + (lane >> 2);
#pragma unroll
        for (int n8 = 0; n8 < 4; n8++) {
            int col = warpCol + n8 * 8 + 2 * (lane & 3);
            float* c = acc[mt][n8];
            *(float2*)&Cs[r0 * 128 + col]       = make_float2(c[0], c[1]);
            *(float2*)&Cs[(r0 + 8) * 128 + col] = make_float2(c[2], c[3]);
        }
    }
    __syncthreads();
    __nv_bfloat16* X2h_w = g_X2h[par ^ 1];
    __nv_bfloat16* X2l_w = g_X2l[par ^ 1];
#pragma unroll
    for (int it = 0; it < 8; it++) {
        int cell = tid + 512 * it;
        int row = cell >> 5, jq = cell & 31;
        int grow = rowBase + row;
        int j = by * 32 + jq;
        float4 gt = *(const float4*)&Cs[row * 128 + jq * 4];   // i,f,g,o
        size_t idx = (size_t)grow * HID + j;
        float ig = gt.x + g_bias[j];
        float fg = gt.y + g_bias[HID + j];
        float gg = gt.z + g_bias[2 * HID + j];
        float og = gt.w + g_bias[3 * HID + j];
        float cn = sigf(fg) * g_c[idx] + sigf(ig) * tanhf(gg);
        g_c[idx] = cn;
        float hv = sigf(og) * tanhf(cn);
        hout[idx] = hv;
        __nv_bfloat16 hb = __float2bfloat16(hv);
        X2h_w[(size_t)grow * 256 + 128 + j] = hb;
        X2l_w[(size_t)grow * 256 + 128 + j] = __float2bfloat16(hv - __bfloat162float(hb));
    }
}

// ---------------- output: softmax(h @ W_out^T) ----------------
__global__ void out_kernel(const float* __restrict__ hin,
                           const float* __restrict__ W_out,
                           float* __restrict__ out) {
    int v = (blockIdx.x * blockDim.x + threadIdx.x) >> 5;
    int lane = threadIdx.x & 31;
    if (v >= N_VARS) return;
    float p0 = 0.f, p1 = 0.f, p2 = 0.f;
#pragma unroll
    for (int q = 0; q < 4; q++) {
        int col = lane + q * 32;
        float hv = hin[(size_t)v * HID + col];
        p0 = fmaf(hv, __ldg(&W_out[col]), p0);
        p1 = fmaf(hv, __ldg(&W_out[HID + col]), p1);
        p2 = fmaf(hv, __ldg(&W_out[2 * HID + col]), p2);
    }
#pragma unroll
    for (int o = 16; o > 0; o >>= 1) {
        p0 += __shfl_xor_sync(0xffffffffu, p0, o);
        p1 += __shfl_xor_sync(0xffffffffu, p1, o);
        p2 += __shfl_xor_sync(0xffffffffu, p2, o);
    }
    if (lane == 0) {
        float m = fmaxf(p0, fmaxf(p1, p2));
        float e0 = expf(p0 - m), e1 = expf(p1 - m), e2 = expf(p2 - m);
        float inv = 1.f / (e0 + e1 + e2);
        out[v * 3 + 0] = e0 * inv;
        out[v * 3 + 1] = e1 * inv;
        out[v * 3 + 2] = e2 * inv;
    }
}

// ---------------- launch ----------------
extern "C" void kernel_launch(void* const* d_in, const int* in_sizes, int n_in,
                              void* d_out, int out_size) {
    const float* h0      = (const float*)d_in[0];
    const float* var_reg = (const float*)d_in[1];
    const float* W_msg   = (const float*)d_in[2];
    const float* gamma   = (const float*)d_in[3];
    const float* beta    = (const float*)d_in[4];
    const float* W_ih    = (const float*)d_in[5];
    const float* W_hh    = (const float*)d_in[6];
    const float* b_ih    = (const float*)d_in[7];
    const float* b_hh    = (const float*)d_in[8];
    const float* W_out   = (const float*)d_in[9];
    const int*   ei      = (const int*)d_in[10];
    (void)in_sizes; (void)n_in;

    cudaFuncSetAttribute(rec_mma,   cudaFuncAttributeMaxDynamicSharedMemorySize, SMEMSZ);
    cudaFuncSetAttribute(gates_mma, cudaFuncAttributeMaxDynamicSharedMemorySize, SMEMSZ);

    float *hA, *hB, *cbuf, *stats;
    int *degi, *cur;
    cudaGetSymbolAddress((void**)&hA, g_hA);
    cudaGetSymbolAddress((void**)&hB, g_hB);
    cudaGetSymbolAddress((void**)&cbuf, g_c);
    cudaGetSymbolAddress((void**)&degi, g_degi);
    cudaGetSymbolAddress((void**)&cur, g_cur);
    cudaGetSymbolAddress((void**)&stats, g_stats);

    cudaStream_t s = 0;
    cudaMemcpyAsync(hA, h0, (size_t)N_VARS * HID * sizeof(float),
                    cudaMemcpyDeviceToDevice, s);
    cudaMemsetAsync(hA + (size_t)N_VARS * HID, 0,
                    (size_t)(NP - N_VARS) * HID * sizeof(float), s);
    cudaMemsetAsync(cbuf, 0, (size_t)NP * HID * sizeof(float), s);
    cudaMemsetAsync(degi, 0, (size_t)NP * sizeof(int), s);
    cudaMemsetAsync(cur, 0, (size_t)NP * sizeof(int), s);
    cudaMemsetAsync(stats, 0, 2 * HID * sizeof(float), s);

    prep_kernel<<<512, 256, 0, s>>>(W_msg, W_ih, W_hh, b_ih, b_hh);
    degcnt_kernel<<<(2 * N_EDGES + 255) / 256, 256, 0, s>>>(ei);
    scan_kernel<<<1, 1024, 0, s>>>();
    fill_kernel<<<(2 * N_EDGES + 255) / 256, 256, 0, s>>>(ei);
    h0split<<<(NP * 16 + 255) / 256, 256, 0, s>>>(hA);

    const float* hin = hA;
    float* hout = hB;
    for (int st = 0; st < STEPS; ++st) {
        int par = st & 1;
        gather_kernel<<<(N_VARS * 32 + 255) / 256, 256, 0, s>>>(hin);
        rec_mma<<<NBLK, 512, SMEMSZ, s>>>(var_reg);
        x2_convert<<<(NP * 16 + 255) / 256, 256, 0, s>>>(par, gamma, beta);
        gates_mma<<<dim3(4, NBLK), 512, SMEMSZ, s>>>(hout, par);
        const float* tmp = hout;
        hout = (float*)hin;
        hin = tmp;
    }
    out_kernel<<<(N_VARS * 32 + 255) / 256, 256, 0, s>>>(hin, W_out, (float*)d_out);
}

// round 15
// speedup vs baseline: 1.0648x; 1.0648x over previous
#include <cuda_runtime.h>
#include <cuda_bf16.h>
#include <math.h>
#include <stdint.h>

#define N_VARS 50000
#define HID 128
#define N_EDGES 400000
#define NP 50048            // 391 * 128
#define NBLK (NP / 128)     // 391
#define STEPS 4
#define BN_EPS 1e-5f

// ---------------- static device scratch ----------------
__device__ float g_hA[NP * HID];
__device__ float g_hB[NP * HID];
__device__ float g_c[NP * HID];
__device__ float g_rec[NP * HID];
__device__ float g_degf[NP];
__device__ int   g_degi[NP];
__device__ int   g_off[NP + 1];
__device__ int   g_cur[NP];
__device__ int   g_adj[2 * N_EDGES];
__device__ __align__(16) __nv_bfloat16 g_W1h[128 * 256];   // rec weights  [n][k]
__device__ __align__(16) __nv_bfloat16 g_W1l[128 * 256];
__device__ __align__(16) __nv_bfloat16 g_W2h[512 * 256];   // gate weights [n=4j+g][k]
__device__ __align__(16) __nv_bfloat16 g_W2l[512 * 256];
__device__ __align__(16) __nv_bfloat16 g_X1h[NP * 256];    // [agg | deg*h] hi
__device__ __align__(16) __nv_bfloat16 g_X1l[NP * 256];
// ping-pong buffers: [BN(rec) | h] — gates reads par, writes h-half of par^1
__device__ __align__(16) __nv_bfloat16 g_X2h[2][NP * 256];
__device__ __align__(16) __nv_bfloat16 g_X2l[2][NP * 256];
__device__ float g_bias[4 * HID];
__device__ float g_stats[2 * HID];

__device__ __forceinline__ float sigf(float x) { return 1.0f / (1.0f + expf(-x)); }

__device__ __forceinline__ uint32_t smem_u32(const void* p) {
    uint32_t a;
    asm("{ .reg .u64 t; cvta.to.shared.u64 t, %1; cvt.u32.u64 %0, t; }" : "=r"(a) : "l"(p));
    return a;
}
// SW64 swizzle for 64-byte smem rows (conflict-free ldmatrix)
#define SWZ64(o) ((o) ^ (((o) >> 3) & 0x30))

#define LDSM4(R, A) \
    asm volatile("ldmatrix.sync.aligned.m8n8.x4.shared.b16 {%0,%1,%2,%3}, [%4];" \
                 : "=r"((R)[0]), "=r"((R)[1]), "=r"((R)[2]), "=r"((R)[3]) : "r"(A))

#define MMA(C, A, B0, B1) \
    asm volatile("mma.sync.aligned.m16n8k16.row.col.f32.bf16.bf16.f32 " \
                 "{%0,%1,%2,%3},{%4,%5,%6,%7},{%8,%9},{%0,%1,%2,%3};" \
                 : "+f"((C)[0]), "+f"((C)[1]), "+f"((C)[2]), "+f"((C)[3]) \
                 : "r"((A)[0]), "r"((A)[1]), "r"((A)[2]), "r"((A)[3]), "r"(B0), "r"(B1))

#define CP16(dst_u32, src_ptr) \
    asm volatile("cp.async.cg.shared.global [%0], [%1], 16;" \
                 :: "r"(dst_u32), "l"(src_ptr))
#define CP_COMMIT() asm volatile("cp.async.commit_group;")
#define CP_WAIT(n)  asm volatile("cp.async.wait_group %0;" :: "n"(n))

union Pack8 { __nv_bfloat16 b[8]; uint4 u; };
__device__ __forceinline__ void split8(float4 a, float4 b, uint4& hi, uint4& lo) {
    float v[8] = {a.x, a.y, a.z, a.w, b.x, b.y, b.z, b.w};
    Pack8 ph, pl;
#pragma unroll
    for (int i = 0; i < 8; i++) {
        __nv_bfloat16 h = __float2bfloat16(v[i]);
        ph.b[i] = h;
        pl.b[i] = __float2bfloat16(v[i] - __bfloat162float(h));
    }
    hi = ph.u; lo = pl.u;
}
union Pack4 { __nv_bfloat16 b[4]; uint2 u; };
__device__ __forceinline__ void split4(float4 a, uint2& hi, uint2& lo) {
    float v[4] = {a.x, a.y, a.z, a.w};
    Pack4 ph, pl;
#pragma unroll
    for (int i = 0; i < 4; i++) {
        __nv_bfloat16 h = __float2bfloat16(v[i]);
        ph.b[i] = h;
        pl.b[i] = __float2bfloat16(v[i] - __bfloat162float(h));
    }
    hi = ph.u; lo = pl.u;
}

// 32-KB stages: A_hi@0, A_lo@8K, B_hi@16K, B_lo@24K — each tile 128 rows x 32 k (64B rows)
#define T_A_HI 0
#define T_A_LO 8192
#define T_B_HI 16384
#define T_B_LO 24576
#define STAGE_SZ 32768
#define SMEMSZ (1024 + 3 * STAGE_SZ)

// ---------------- prep: bf16-split weights, fused bias ----------------
__global__ void prep_kernel(const float* __restrict__ W_msg,
                            const float* __restrict__ W_ih,
                            const float* __restrict__ W_hh,
                            const float* __restrict__ b_ih,
                            const float* __restrict__ b_hh) {
    int t = blockIdx.x * blockDim.x + threadIdx.x;
    int stride = gridDim.x * blockDim.x;
    for (int i = t; i < 128 * 256; i += stride) {
        float w = W_msg[i];
        __nv_bfloat16 h = __float2bfloat16(w);
        g_W1h[i] = h;
        g_W1l[i] = __float2bfloat16(w - __bfloat162float(h));
    }
    for (int i = t; i < 512 * 256; i += stride) {
        int n = i >> 8, k = i & 255;
        int j = n >> 2, g = n & 3;
        int wrow = g * HID + j;
        float w = (k < HID) ? W_ih[wrow * HID + k] : W_hh[wrow * HID + (k - HID)];
        __nv_bfloat16 h = __float2bfloat16(w);
        g_W2h[i] = h;
        g_W2l[i] = __float2bfloat16(w - __bfloat162float(h));
    }
    for (int i = t; i < 4 * HID; i += stride) g_bias[i] = b_ih[i] + b_hh[i];
}

// ---------------- CSR build ----------------
__global__ void degcnt_kernel(const int* __restrict__ ei) {
    int i = blockIdx.x * blockDim.x + threadIdx.x;
    if (i < 2 * N_EDGES) atomicAdd(&g_degi[ei[i]], 1);
}

__global__ void scan_kernel() {       // single block, 1024 threads
    __shared__ int part[1024];
    int t = threadIdx.x;
    const int CH = (N_VARS + 1023) / 1024;
    int base = t * CH;
    int s = 0;
    for (int i = 0; i < CH; i++) {
        int idx = base + i;
        if (idx < N_VARS) s += g_degi[idx];
    }
    part[t] = s;
    __syncthreads();
    int val = s;
#pragma unroll
    for (int d = 1; d < 1024; d <<= 1) {
        int v = (t >= d) ? part[t - d] : 0;
        __syncthreads();
        part[t] += v;
        __syncthreads();
    }
    int excl = part[t] - val;
    int run = excl;
    for (int i = 0; i < CH; i++) {
        int idx = base + i;
        if (idx < N_VARS) {
            g_off[idx] = run;
            int d = g_degi[idx];
            g_degf[idx] = (float)d;
            run += d;
        }
    }
    if (t == 1023) g_off[N_VARS] = run;
}

__global__ void fill_kernel(const int* __restrict__ ei) {
    int i = blockIdx.x * blockDim.x + threadIdx.x;
    if (i >= 2 * N_EDGES) return;
    int s, d;
    if (i < N_EDGES) { s = ei[i]; d = ei[N_EDGES + i]; }
    else             { s = ei[i]; d = ei[i - N_EDGES]; }
    int pos = atomicAdd(&g_cur[d], 1);
    g_adj[g_off[d] + pos] = s;
}

// ---------------- h0 split -> X2[0] h-part (once) ----------------
__global__ void h0split(const float* __restrict__ hin) {
    int idx = blockIdx.x * blockDim.x + threadIdx.x;
    if (idx >= NP * 16) return;
    int row = idx >> 4, i = idx & 15;
    const float* src = &hin[(size_t)row * HID + i * 8];
    float4 v0 = *(const float4*)src, v1 = *(const float4*)(src + 4);
    uint4 hi, lo; split8(v0, v1, hi, lo);
    ((uint4*)g_X2h[0])[row * 32 + 16 + i] = hi;
    ((uint4*)g_X2l[0])[row * 32 + 16 + i] = lo;
}

// ---------------- CSR gather -> X1 = split([agg | deg*h]) ----------------
__global__ void gather_kernel(const float* __restrict__ hin) {
    int w = (blockIdx.x * blockDim.x + threadIdx.x) >> 5;
    int lane = threadIdx.x & 31;
    if (w >= N_VARS) return;
    int e = g_off[w], end = g_off[w + 1];
    int c4 = lane * 4;
    float4 s0 = make_float4(0, 0, 0, 0), s1 = make_float4(0, 0, 0, 0);
    float4 s2 = make_float4(0, 0, 0, 0), s3 = make_float4(0, 0, 0, 0);
    for (; e + 4 <= end; e += 4) {
        int u0 = g_adj[e], u1 = g_adj[e + 1], u2 = g_adj[e + 2], u3 = g_adj[e + 3];
        float4 a = *(const float4*)&hin[(size_t)u0 * HID + c4];
        float4 b = *(const float4*)&hin[(size_t)u1 * HID + c4];
        float4 c = *(const float4*)&hin[(size_t)u2 * HID + c4];
        float4 d = *(const float4*)&hin[(size_t)u3 * HID + c4];
        s0.x += a.x; s0.y += a.y; s0.z += a.z; s0.w += a.w;
        s1.x += b.x; s1.y += b.y; s1.z += b.z; s1.w += b.w;
        s2.x += c.x; s2.y += c.y; s2.z += c.z; s2.w += c.w;
        s3.x += d.x; s3.y += d.y; s3.z += d.z; s3.w += d.w;
    }
    for (; e < end; e++) {
        int u = g_adj[e];
        float4 a = *(const float4*)&hin[(size_t)u * HID + c4];
        s0.x += a.x; s0.y += a.y; s0.z += a.z; s0.w += a.w;
    }
    s0.x += s1.x + s2.x + s3.x; s0.y += s1.y + s2.y + s3.y;
    s0.z += s1.z + s2.z + s3.z; s0.w += s1.w + s2.w + s3.w;
    uint2 hi, lo;
    split4(s0, hi, lo);
    ((uint2*)g_X1h)[w * 64 + lane] = hi;        // k = c4
    ((uint2*)g_X1l)[w * 64 + lane] = lo;
    float d = g_degf[w];
    float4 hv = *(const float4*)&hin[(size_t)w * HID + c4];
    hv.x *= d; hv.y *= d; hv.z *= d; hv.w *= d;
    split4(hv, hi, lo);
    ((uint2*)g_X1h)[w * 64 + 32 + lane] = hi;   // k = 128 + c4
    ((uint2*)g_X1l)[w * 64 + 32 + lane] = lo;
}

// ---------------- cp.async tile staging: one 32-k chunk (A+B, hi+lo) ----------------
// 512 threads, 512 items: row = tid>>2 (128 rows), i = tid&3 (4 x 16B = 64B row)
__device__ __forceinline__ void stage_tiles(uint32_t sbase,
                                            const uint4* __restrict__ Ah,
                                            const uint4* __restrict__ Al,
                                            const uint4* __restrict__ Bh,
                                            const uint4* __restrict__ Bl,
                                            int aBase4, int bBase4, int k4, int tid) {
    int row = tid >> 2, i = tid & 3;
    uint32_t sw = SWZ64((uint32_t)(row * 64 + i * 16));
    int ga = aBase4 + row * 32 + k4 + i;
    int gb = bBase4 + row * 32 + k4 + i;
    CP16(sbase + T_A_HI + sw, Ah + ga);
    CP16(sbase + T_A_LO + sw, Al + ga);
    CP16(sbase + T_B_HI + sw, Bh + gb);
    CP16(sbase + T_B_LO + sw, Bl + gb);
}

// ---------------- warp-tile compute core (one K-chunk of 32), 32x32 warp tile ----------------
__device__ __forceinline__ void chunk_compute(uint32_t sb, int warpRow, int warpCol,
                                              int lane, float acc[2][4][4]) {
#pragma unroll
    for (int ks = 0; ks < 2; ks++) {
        uint32_t aH[2][4], aL[2][4];
#pragma unroll
        for (int mt = 0; mt < 2; mt++) {
            uint32_t off = (uint32_t)((warpRow + mt * 16 + (lane & 15)) * 64
                                      + ks * 32 + ((lane >> 4) & 1) * 16);
            uint32_t sw = SWZ64(off);
            LDSM4(aH[mt], sb + T_A_HI + sw);
            LDSM4(aL[mt], sb + T_A_LO + sw);
        }
#pragma unroll
        for (int np = 0; np < 2; np++) {
            uint32_t bH[4], bL[4];
            uint32_t off = (uint32_t)((warpCol + np * 16 + ((lane >> 4) & 1) * 8 + (lane & 7)) * 64
                                      + ks * 32 + ((lane >> 3) & 1) * 16);
            uint32_t sw = SWZ64(off);
            LDSM4(bH, sb + T_B_HI + sw);
            LDSM4(bL, sb + T_B_LO + sw);
#pragma unroll
            for (int mt = 0; mt < 2; mt++) {
#pragma unroll
                for (int nt = 0; nt < 2; nt++) {
                    float* c = acc[mt][np * 2 + nt];
                    MMA(c, aH[mt], bH[nt * 2], bH[nt * 2 + 1]);
                    MMA(c, aH[mt], bL[nt * 2], bL[nt * 2 + 1]);
                    MMA(c, aL[mt], bH[nt * 2], bH[nt * 2 + 1]);
                }
            }
        }
    }
}

// ---------------- shared GEMM pipeline: 3-stage, 8 chunks of K=32 ----------------
#define GEMM_PIPELINE(Ah, Al, Bh, Bl, ABASE, BBASE)                                    \
    stage_tiles(sb,                Ah, Al, Bh, Bl, ABASE, BBASE, 0, tid); CP_COMMIT(); \
    stage_tiles(sb + STAGE_SZ,     Ah, Al, Bh, Bl, ABASE, BBASE, 4, tid); CP_COMMIT(); \
    stage_tiles(sb + 2 * STAGE_SZ, Ah, Al, Bh, Bl, ABASE, BBASE, 8, tid); CP_COMMIT(); \
    _Pragma("unroll")                                                                  \
    for (int c = 0; c < 8; c++) {                                                      \
        if (c < 6) { CP_WAIT(2); } else if (c == 6) { CP_WAIT(1); } else { CP_WAIT(0);}\
        __syncthreads();                                                               \
        chunk_compute(sb + (c % 3) * STAGE_SZ, warpRow, warpCol, lane, acc);           \
        __syncthreads();                                                               \
        if (c < 5) {                                                                   \
            stage_tiles(sb + (c % 3) * STAGE_SZ, Ah, Al, Bh, Bl, ABASE, BBASE,         \
                        (c + 3) * 4, tid);                                             \
            CP_COMMIT();                                                               \
        }                                                                              \
    }

// ---------------- rec = (X1 @ W1^T) * var_reg, with fused BN stats ----------------
__global__ void __launch_bounds__(512, 2)
rec_mma(const float* __restrict__ var_reg) {
    extern __shared__ char smraw[];
    uint32_t sb0 = smem_u32(smraw);
    uint32_t sb = (sb0 + 1023) & ~1023u;
    const int tid = threadIdx.x;
    const int wid = tid >> 5, lane = tid & 31;
    const int rowBase = blockIdx.x * 128;
    const int warpRow = (wid >> 2) * 32, warpCol = (wid & 3) * 32;

    float acc[2][4][4];
#pragma unroll
    for (int m = 0; m < 2; m++)
#pragma unroll
        for (int n = 0; n < 4; n++)
#pragma unroll
            for (int c = 0; c < 4; c++) acc[m][n][c] = 0.f;

    GEMM_PIPELINE((const uint4*)g_X1h, (const uint4*)g_X1l,
                  (const uint4*)g_W1h, (const uint4*)g_W1l,
                  rowBase * 32, 0)

    // epilogue: scale by var_reg, store rec, fused column stats
    float s[4][2] = {}, q[4][2] = {};
#pragma unroll
    for (int mt = 0; mt < 2; mt++) {
        int r0 = rowBase + warpRow + mt * 16 + (lane >> 2);
        int r1 = r0 + 8;
        float vr0 = (r0 < N_VARS) ? var_reg[r0] : 0.f;
        float vr1 = (r1 < N_VARS) ? var_reg[r1] : 0.f;
#pragma unroll
        for (int n8 = 0; n8 < 4; n8++) {
            int col = warpCol + n8 * 8 + 2 * (lane & 3);
            float* c = acc[mt][n8];
            float v00 = c[0] * vr0, v01 = c[1] * vr0;
            float v10 = c[2] * vr1, v11 = c[3] * vr1;
            *(float2*)&g_rec[(size_t)r0 * HID + col] = make_float2(v00, v01);
            *(float2*)&g_rec[(size_t)r1 * HID + col] = make_float2(v10, v11);
            s[n8][0] += v00 + v10;  q[n8][0] += v00 * v00 + v10 * v10;
            s[n8][1] += v01 + v11;  q[n8][1] += v01 * v01 + v11 * v11;
        }
    }
#pragma unroll
    for (int o = 4; o <= 16; o <<= 1) {
#pragma unroll
        for (int n8 = 0; n8 < 4; n8++) {
#pragma unroll
            for (int p = 0; p < 2; p++) {
                s[n8][p] += __shfl_xor_sync(0xffffffffu, s[n8][p], o);
                q[n8][p] += __shfl_xor_sync(0xffffffffu, q[n8][p], o);
            }
        }
    }
    if (lane < 4) {
#pragma unroll
        for (int n8 = 0; n8 < 4; n8++) {
#pragma unroll
            for (int p = 0; p < 2; p++) {
                int col = warpCol + n8 * 8 + 2 * lane + p;
                atomicAdd(&g_stats[col], s[n8][p]);
                atomicAdd(&g_stats[HID + col], q[n8][p]);
            }
        }
    }
}

// ---------------- X2[par] rec-half = bf16-split of BN(rec); BN coeffs in-block ----------------
__global__ void x2_convert(int par, const float* __restrict__ gamma,
                           const float* __restrict__ beta) {
    __shared__ float sA[HID], sB[HID];
    int t = threadIdx.x;
    if (t < HID) {
        float mean = g_stats[t] * (1.0f / N_VARS);
        float var = g_stats[HID + t] * (1.0f / N_VARS) - mean * mean;
        float a = gamma[t] * rsqrtf(var + BN_EPS);
        sA[t] = a;
        sB[t] = beta[t] - mean * a;
    }
    __syncthreads();
    int idx = blockIdx.x * blockDim.x + t;
    if (idx >= NP * 16) return;
    int row = idx >> 4;
    int k = (idx & 15) * 8;
    const float* src = &g_rec[(size_t)row * HID + k];
    float4 v0 = *(const float4*)src, v1 = *(const float4*)(src + 4);
    float4 a0 = *(const float4*)&sA[k], a1 = *(const float4*)&sA[k + 4];
    float4 b0 = *(const float4*)&sB[k], b1 = *(const float4*)&sB[k + 4];
    v0.x = fmaf(v0.x, a0.x, b0.x); v0.y = fmaf(v0.y, a0.y, b0.y);
    v0.z = fmaf(v0.z, a0.z, b0.z); v0.w = fmaf(v0.w, a0.w, b0.w);
    v1.x = fmaf(v1.x, a1.x, b1.x); v1.y = fmaf(v1.y, a1.y, b1.y);
    v1.z = fmaf(v1.z, a1.z, b1.z); v1.w = fmaf(v1.w, a1.w, b1.w);
    uint4 hi, lo; split8(v0, v1, hi, lo);
    ((uint4*)g_X2h[par])[row * 32 + (idx & 15)] = hi;
    ((uint4*)g_X2l[par])[row * 32 + (idx & 15)] = lo;
}

// ---------------- gates = X2[par] @ W2^T + LSTM pointwise; split(h) -> X2[par^1] ----------------
__global__ void __launch_bounds__(512, 2)
gates_mma(float* __restrict__ hout, int par) {
    extern __shared__ char smraw[];
    uint32_t sb0 = smem_u32(smraw);
    uint32_t sb = (sb0 + 1023) & ~1023u;
    char* smp = smraw + (sb - sb0);
    const int tid = threadIdx.x;
    const int wid = tid >> 5, lane = tid & 31;
    const int bx = blockIdx.x;
    const int by = blockIdx.y;
    const int rowBase = bx * 128;
    const int warpRow = (wid >> 2) * 32, warpCol = (wid & 3) * 32;

    // reset BN stats for the next step (after x2_convert consumed them)
    if (bx == 0 && by == 0 && tid < 2 * HID) g_stats[tid] = 0.f;

    float acc[2][4][4];
#pragma unroll
    for (int m = 0; m < 2; m++)
#pragma unroll
        for (int n = 0; n < 4; n++)
#pragma unroll
            for (int c = 0; c < 4; c++) acc[m][n][c] = 0.f;

    GEMM_PIPELINE((const uint4*)g_X2h[par], (const uint4*)g_X2l[par],
                  (const uint4*)g_W2h, (const uint4*)g_W2l,
                  rowBase * 32, by * 128 * 32)

    // stage gate tile to smem overlay, then fused LSTM pointwise
    float* Cs = (float*)smp;                   // 128 x 128 fp32 = 64KB ≤ 96KB stages
#pragma unroll
    for (int mt = 0; mt < 2; mt++) {
        int r0 = warpRow + mt * 16 + (lane >> 2);
#pragma unroll
        for (int n8 = 0; n8 < 4; n8++) {
            int col = warpCol + n8 * 8 + 2 * (lane & 3);
            float* c = acc[mt][n8];
            *(float2*)&Cs[r0 * 128 + col]       = make_float2(c[0], c[1]);
            *(float2*)&Cs[(r0 + 8) * 128 + col] = make_float2(c[2], c[3]);
        }
    }
    __syncthreads();
    __nv_bfloat16* X2h_w = g_X2h[par ^ 1];
    __nv_bfloat16* X2l_w = g_X2l[par ^ 1];
#pragma unroll
    for (int it = 0; it < 8; it++) {
        int cell = tid + 512 * it;
        int row = cell >> 5, jq = cell & 31;
        int grow = rowBase + row;
        int j = by * 32 + jq;
        float4 gt = *(const float4*)&Cs[row * 128 + jq * 4];   // i,f,g,o
        size_t idx = (size_t)grow * HID + j;
        float ig = gt.x + g_bias[j];
        float fg = gt.y + g_bias[HID + j];
        float gg = gt.z + g_bias[2 * HID + j];
        float og = gt.w + g_bias[3 * HID + j];
        float cn = sigf(fg) * g_c[idx] + sigf(ig) * tanhf(gg);
        g_c[idx] = cn;
        float hv = sigf(og) * tanhf(cn);
        hout[idx] = hv;
        __nv_bfloat16 hb = __float2bfloat16(hv);
        X2h_w[(size_t)grow * 256 + 128 + j] = hb;
        X2l_w[(size_t)grow * 256 + 128 + j] = __float2bfloat16(hv - __bfloat162float(hb));
    }
}

// ---------------- output: softmax(h @ W_out^T) ----------------
__global__ void out_kernel(const float* __restrict__ hin,
                           const float* __restrict__ W_out,
                           float* __restrict__ out) {
    int v = (blockIdx.x * blockDim.x + threadIdx.x) >> 5;
    int lane = threadIdx.x & 31;
    if (v >= N_VARS) return;
    float p0 = 0.f, p1 = 0.f, p2 = 0.f;
#pragma unroll
    for (int q = 0; q < 4; q++) {
        int col = lane + q * 32;
        float hv = hin[(size_t)v * HID + col];
        p0 = fmaf(hv, __ldg(&W_out[col]), p0);
        p1 = fmaf(hv, __ldg(&W_out[HID + col]), p1);
        p2 = fmaf(hv, __ldg(&W_out[2 * HID + col]), p2);
    }
#pragma unroll
    for (int o = 16; o > 0; o >>= 1) {
        p0 += __shfl_xor_sync(0xffffffffu, p0, o);
        p1 += __shfl_xor_sync(0xffffffffu, p1, o);
        p2 += __shfl_xor_sync(0xffffffffu, p2, o);
    }
    if (lane == 0) {
        float m = fmaxf(p0, fmaxf(p1, p2));
        float e0 = expf(p0 - m), e1 = expf(p1 - m), e2 = expf(p2 - m);
        float inv = 1.f / (e0 + e1 + e2);
        out[v * 3 + 0] = e0 * inv;
        out[v * 3 + 1] = e1 * inv;
        out[v * 3 + 2] = e2 * inv;
    }
}

// ---------------- launch ----------------
extern "C" void kernel_launch(void* const* d_in, const int* in_sizes, int n_in,
                              void* d_out, int out_size) {
    const float* h0      = (const float*)d_in[0];
    const float* var_reg = (const float*)d_in[1];
    const float* W_msg   = (const float*)d_in[2];
    const float* gamma   = (const float*)d_in[3];
    const float* beta    = (const float*)d_in[4];
    const float* W_ih    = (const float*)d_in[5];
    const float* W_hh    = (const float*)d_in[6];
    const float* b_ih    = (const float*)d_in[7];
    const float* b_hh    = (const float*)d_in[8];
    const float* W_out   = (const float*)d_in[9];
    const int*   ei      = (const int*)d_in[10];
    (void)in_sizes; (void)n_in;

    cudaFuncSetAttribute(rec_mma,   cudaFuncAttributeMaxDynamicSharedMemorySize, SMEMSZ);
    cudaFuncSetAttribute(gates_mma, cudaFuncAttributeMaxDynamicSharedMemorySize, SMEMSZ);

    float *hA, *hB, *cbuf, *stats;
    int *degi, *cur;
    cudaGetSymbolAddress((void**)&hA, g_hA);
    cudaGetSymbolAddress((void**)&hB, g_hB);
    cudaGetSymbolAddress((void**)&cbuf, g_c);
    cudaGetSymbolAddress((void**)&degi, g_degi);
    cudaGetSymbolAddress((void**)&cur, g_cur);
    cudaGetSymbolAddress((void**)&stats, g_stats);

    cudaStream_t s = 0;
    cudaMemcpyAsync(hA, h0, (size_t)N_VARS * HID * sizeof(float),
                    cudaMemcpyDeviceToDevice, s);
    cudaMemsetAsync(hA + (size_t)N_VARS * HID, 0,
                    (size_t)(NP - N_VARS) * HID * sizeof(float), s);
    cudaMemsetAsync(cbuf, 0, (size_t)NP * HID * sizeof(float), s);
    cudaMemsetAsync(degi, 0, (size_t)NP * sizeof(int), s);
    cudaMemsetAsync(cur, 0, (size_t)NP * sizeof(int), s);
    cudaMemsetAsync(stats, 0, 2 * HID * sizeof(float), s);

    prep_kernel<<<512, 256, 0, s>>>(W_msg, W_ih, W_hh, b_ih, b_hh);
    degcnt_kernel<<<(2 * N_EDGES + 255) / 256, 256, 0, s>>>(ei);
    scan_kernel<<<1, 1024, 0, s>>>();
    fill_kernel<<<(2 * N_EDGES + 255) / 256, 256, 0, s>>>(ei);
    h0split<<<(NP * 16 + 255) / 256, 256, 0, s>>>(hA);

    const float* hin = hA;
    float* hout = hB;
    for (int st = 0; st < STEPS; ++st) {
        int par = st & 1;
        gather_kernel<<<(N_VARS * 32 + 255) / 256, 256, 0, s>>>(hin);
        rec_mma<<<NBLK, 512, SMEMSZ, s>>>(var_reg);
        x2_convert<<<(NP * 16 + 255) / 256, 256, 0, s>>>(par, gamma, beta);
        gates_mma<<<dim3(NBLK, 4), 512, SMEMSZ, s>>>(hout, par);
        const float* tmp = hout;
        hout = (float*)hin;
        hin = tmp;
    }
    out_kernel<<<(N_VARS * 32 + 255) / 256, 256, 0, s>>>(hin, W_out, (float*)d_out);
}